// round 11
// baseline (speedup 1.0000x reference)
#include <cuda_runtime.h>
#include <cuda_fp16.h>

// Problem constants (from reference)
#define BB 16
#define AA 128
#define PP 8192
#define TT 5
#define K_LOG2E 1.4426950408889634f   // log2(e); TEMPERATURE = 1.0
#define CLIP    0.3f

#define THREADS 256        // 8 warps/block
#define QPW 32             // queries per warp: two m16 tiles
#define QPB (8 * QPW)      // 256 queries per block
#define NCOL 24            // B columns: 5 types * 4 (S,Gx,Gy,Gz), padded to 24
#define KPAD 136           // padded k-stride (halves): bank-conflict-free

__device__ __forceinline__ float sqrtf_a(float x) {
    float y; asm("sqrt.approx.ftz.f32 %0, %1;" : "=f"(y) : "f"(x)); return y;
}
__device__ __forceinline__ float rcpf_a(float x) {
    float y; asm("rcp.approx.ftz.f32 %0, %1;" : "=f"(y) : "f"(x)); return y;
}
__device__ __forceinline__ float rsqrtf_a(float x) {
    float y; asm("rsqrt.approx.ftz.f32 %0, %1;" : "=f"(y) : "f"(x)); return y;
}
// cvt two f32 -> f16x2; FIRST operand lands in the HIGH half
__device__ __forceinline__ unsigned cvt_f16x2(float hi, float lo) {
    unsigned r; asm("cvt.rn.f16x2.f32 %0, %1, %2;" : "=r"(r) : "f"(hi), "f"(lo)); return r;
}
__device__ __forceinline__ unsigned ex2_f16x2(unsigned x) {
    unsigned r; asm("ex2.approx.f16x2 %0, %1;" : "=r"(r) : "r"(x)); return r;
}
// D += A(16x16 f16) * B(16x8 f16), f32 accumulate
__device__ __forceinline__ void mma16816(float* c,
                                         unsigned a0, unsigned a1, unsigned a2, unsigned a3,
                                         unsigned b0, unsigned b1) {
    asm volatile(
        "mma.sync.aligned.m16n8k16.row.col.f32.f16.f16.f32 "
        "{%0,%1,%2,%3}, {%4,%5,%6,%7}, {%8,%9}, {%0,%1,%2,%3};"
        : "+f"(c[0]), "+f"(c[1]), "+f"(c[2]), "+f"(c[3])
        : "r"(a0), "r"(a1), "r"(a2), "r"(a3), "r"(b0), "r"(b1));
}

__global__ void __launch_bounds__(THREADS)
gnf_kernel(const float* __restrict__ coords,     // [B, A, 3] f32
           const int*   __restrict__ types_raw,  // [B, A] int32 OR int64 (detected)
           const float* __restrict__ query,      // [B, P, 3] f32
           float*       __restrict__ out)        // [B, P, T, 3] f32
{
    // sAtom[a] = (cx', cy', cz', |c'|^2), c' = c*log2e   -> scalar d^2 dot
    // sBhi/sBlo: B^T [NCOL][KPAD] split-f16; col 4t+{0..3} = (1, cx, cy, cz)
    __shared__ float4 sAtom[AA];
    __shared__ __half sBhi[NCOL * KPAD];
    __shared__ __half sBlo[NCOL * KPAD];

    const int tid = threadIdx.x;
    const int b   = blockIdx.y;

    // ---- zero B matrices
    for (int i = tid; i < NCOL * KPAD / 2; i += THREADS) {
        ((unsigned*)sBhi)[i] = 0u;
        ((unsigned*)sBlo)[i] = 0u;
    }

    // ---- dtype detection (1 LDG/thread); int64 iff all sampled odd words in {0,-1}
    {
        int w = types_raw[2 * (tid & 255) + 1];
        bool okk = (w == 0) || (w == -1);
        const int is64 = __syncthreads_and(okk ? 1 : 0);   // also fences zero-fill

        if (tid < AA) {
            long long tv;
            if (is64) tv = ((const long long*)types_raw)[(long)b * AA + tid];
            else      tv = (long long)types_raw[(long)b * AA + tid];
            const float* c = coords + ((long)b * AA + tid) * 3;

            if (tv >= 0 && tv < TT) {
                float rx = c[0], ry = c[1], rz = c[2];
                float cx = rx * K_LOG2E, cy = ry * K_LOG2E, cz = rz * K_LOG2E;
                sAtom[tid] = make_float4(cx, cy, cz,
                                         fmaf(cx, cx, fmaf(cy, cy, cz * cz)));
                int t4 = (int)tv * 4;
                sBhi[(t4 + 0) * KPAD + tid] = __float2half_rn(1.f);
                float v[3] = {rx, ry, rz};
                #pragma unroll
                for (int j = 0; j < 3; j++) {
                    __half h = __float2half_rn(v[j]);
                    sBhi[(t4 + 1 + j) * KPAD + tid] = h;
                    sBlo[(t4 + 1 + j) * KPAD + tid] =
                        __float2half_rn(v[j] - __half2float(h));
                }
            } else {
                sAtom[tid] = make_float4(0.f, 0.f, 0.f, 1e30f);  // w -> ex2(-inf) = 0
            }
        }
        __syncthreads();
    }

    // ---- warp owns 32 queries: two m16 tiles
    const int warp = tid >> 5;
    const int lane = tid & 31;
    const int r    = lane >> 2;        // 0..7
    const int kq   = (lane & 3) * 2;   // 0,2,4,6
    const int qb   = blockIdx.x * QPB + warp * QPW;

    // query params: rows [m][0]=qb+m*16+r, [m][1]=qb+m*16+r+8
    float nxp[2][2], nyp[2][2], nzp[2][2], qqp[2][2];
    #pragma unroll
    for (int m = 0; m < 2; m++) {
        #pragma unroll
        for (int hh = 0; hh < 2; hh++) {
            const float* qp = query + ((long)b * PP + qb + m * 16 + r + hh * 8) * 3;
            float nx = qp[0] * (-2.f * K_LOG2E);
            float ny = qp[1] * (-2.f * K_LOG2E);
            float nz = qp[2] * (-2.f * K_LOG2E);
            nxp[m][hh] = nx; nyp[m][hh] = ny; nzp[m][hh] = nz;
            qqp[m][hh] = 0.25f * fmaf(nx, nx, fmaf(ny, ny, nz * nz));
        }
    }

    float acc[2][3][4];
    #pragma unroll
    for (int m = 0; m < 2; m++)
        #pragma unroll
        for (int nt = 0; nt < 3; nt++)
            #pragma unroll
            for (int j = 0; j < 4; j++) acc[m][nt][j] = 0.f;

    // ---- main loop: 8 k-tiles of 16 atoms; atoms + B frags shared by both m tiles
    #pragma unroll
    for (int kt = 0; kt < 8; kt++) {
        const int k0 = kt * 16 + kq;
        const float4 cA = sAtom[k0];
        const float4 cB = sAtom[k0 + 1];
        const float4 cC = sAtom[k0 + 8];
        const float4 cD = sAtom[k0 + 9];

        // B fragments once per kt (shared across m)
        unsigned bh0[3], bh1[3], bl0[3], bl1[3];
        #pragma unroll
        for (int nt = 0; nt < 3; nt++) {
            const int bbase = (nt * 8 + r) * KPAD + kt * 16 + kq;
            bh0[nt] = *(const unsigned*)&sBhi[bbase];
            bh1[nt] = *(const unsigned*)&sBhi[bbase + 8];
            bl0[nt] = *(const unsigned*)&sBlo[bbase];
            bl1[nt] = *(const unsigned*)&sBlo[bbase + 8];
        }

        #pragma unroll
        for (int m = 0; m < 2; m++) {
            const float n0x = nxp[m][0], n0y = nyp[m][0], n0z = nzp[m][0], qq0 = qqp[m][0];
            const float n1x = nxp[m][1], n1y = nyp[m][1], n1z = nzp[m][1], qq1 = qqp[m][1];

            float dA0 = fmaf(cA.x, n0x, fmaf(cA.y, n0y, fmaf(cA.z, n0z, cA.w))) + qq0;
            float dB0 = fmaf(cB.x, n0x, fmaf(cB.y, n0y, fmaf(cB.z, n0z, cB.w))) + qq0;
            float dC0 = fmaf(cC.x, n0x, fmaf(cC.y, n0y, fmaf(cC.z, n0z, cC.w))) + qq0;
            float dD0 = fmaf(cD.x, n0x, fmaf(cD.y, n0y, fmaf(cD.z, n0z, cD.w))) + qq0;
            float dA1 = fmaf(cA.x, n1x, fmaf(cA.y, n1y, fmaf(cA.z, n1z, cA.w))) + qq1;
            float dB1 = fmaf(cB.x, n1x, fmaf(cB.y, n1y, fmaf(cB.z, n1z, cB.w))) + qq1;
            float dC1 = fmaf(cC.x, n1x, fmaf(cC.y, n1y, fmaf(cC.z, n1z, cC.w))) + qq1;
            float dD1 = fmaf(cD.x, n1x, fmaf(cD.y, n1y, fmaf(cD.z, n1z, cD.w))) + qq1;

            unsigned a0 = ex2_f16x2(cvt_f16x2(sqrtf_a(dB0), sqrtf_a(dA0)) ^ 0x80008000u);
            unsigned a1 = ex2_f16x2(cvt_f16x2(sqrtf_a(dB1), sqrtf_a(dA1)) ^ 0x80008000u);
            unsigned a2 = ex2_f16x2(cvt_f16x2(sqrtf_a(dD0), sqrtf_a(dC0)) ^ 0x80008000u);
            unsigned a3 = ex2_f16x2(cvt_f16x2(sqrtf_a(dD1), sqrtf_a(dC1)) ^ 0x80008000u);

            #pragma unroll
            for (int nt = 0; nt < 3; nt++) {
                mma16816(acc[m][nt], a0, a1, a2, a3, bh0[nt], bh1[nt]);
                mma16816(acc[m][nt], a0, a1, a2, a3, bl0[nt], bl1[nt]);
            }
        }
    }

    // ---- epilogue per m tile
    #pragma unroll
    for (int m = 0; m < 2; m++) {
        #pragma unroll
        for (int nt = 0; nt < 3; nt++) {
            float c0 = acc[m][nt][0], c1 = acc[m][nt][1],
                  c2 = acc[m][nt][2], c3 = acc[m][nt][3];
            float x0 = __shfl_xor_sync(0xffffffffu, c0, 1);
            float x1 = __shfl_xor_sync(0xffffffffu, c1, 1);
            float x2 = __shfl_xor_sync(0xffffffffu, c2, 1);
            float x3 = __shfl_xor_sync(0xffffffffu, c3, 1);

            const int t = 2 * nt + ((lane & 3) >> 1);
            if (t < TT) {
                float S, Gx, Gy, Gz;
                int q;
                if ((lane & 1) == 0) { S = c0; Gx = c1; Gy = x0; Gz = x1; q = qb + m * 16 + r; }
                else                 { S = x2; Gx = x3; Gy = c2; Gz = c3; q = qb + m * 16 + r + 8; }

                const float* qp = query + ((long)b * PP + q) * 3;
                float gx = 0.f, gy = 0.f, gz = 0.f;
                if (S > 0.f) {
                    float inv = rcpf_a(S);
                    gx = fmaf(Gx, inv, -qp[0]);
                    gy = fmaf(Gy, inv, -qp[1]);
                    gz = fmaf(Gz, inv, -qp[2]);
                    float m2 = fmaf(gx, gx, fmaf(gy, gy, gz * gz));
                    if (m2 > CLIP * CLIP) {
                        float sc = CLIP * rsqrtf_a(m2);
                        gx *= sc; gy *= sc; gz *= sc;
                    }
                }
                float* op = out + (((long)b * PP + q) * TT + t) * 3;
                op[0] = gx; op[1] = gy; op[2] = gz;
            }
        }
    }
}

extern "C" void kernel_launch(void* const* d_in, const int* in_sizes, int n_in,
                              void* d_out, int out_size)
{
    const float* coords = (const float*)d_in[0];   // [16,128,3] f32
    const int*   types  = (const int*)d_in[1];     // [16,128] int32/int64 (detected on device)
    const float* query  = (const float*)d_in[2];   // [16,8192,3] f32
    float*       out    = (float*)d_out;           // [16,8192,5,3] f32

    dim3 grid(PP / QPB, BB);   // (32, 16) = 512 blocks x 256 threads
    gnf_kernel<<<grid, THREADS>>>(coords, types, query, out);
}

// round 12
// speedup vs baseline: 1.0934x; 1.0934x over previous
#include <cuda_runtime.h>
#include <cuda_fp16.h>

// Problem constants (from reference)
#define BB 16
#define AA 128
#define PP 8192
#define TT 5
#define K_LOG2E 1.4426950408889634f   // log2(e); TEMPERATURE = 1.0
#define CLIP    0.3f

#define THREADS 256        // 8 warps/block
#define QPB 128            // queries per block: each warp owns 16 queries
#define NCOL 24            // B columns: 5 types * 4 (S,Gx,Gy,Gz), padded to 24
#define KPAD 136           // padded k-stride (halves): bank-conflict-free

__device__ __forceinline__ float sqrtf_a(float x) {
    float y; asm("sqrt.approx.ftz.f32 %0, %1;" : "=f"(y) : "f"(x)); return y;
}
__device__ __forceinline__ float rcpf_a(float x) {
    float y; asm("rcp.approx.ftz.f32 %0, %1;" : "=f"(y) : "f"(x)); return y;
}
__device__ __forceinline__ float rsqrtf_a(float x) {
    float y; asm("rsqrt.approx.ftz.f32 %0, %1;" : "=f"(y) : "f"(x)); return y;
}
// cvt two f32 -> f16x2; FIRST operand lands in the HIGH half
__device__ __forceinline__ unsigned cvt_f16x2(float hi, float lo) {
    unsigned r; asm("cvt.rn.f16x2.f32 %0, %1, %2;" : "=r"(r) : "f"(hi), "f"(lo)); return r;
}
__device__ __forceinline__ unsigned ex2_f16x2(unsigned x) {
    unsigned r; asm("ex2.approx.f16x2 %0, %1;" : "=r"(r) : "r"(x)); return r;
}
// D += A(16x16 f16) * B(16x8 f16), f32 accumulate
__device__ __forceinline__ void mma16816(float* c,
                                         unsigned a0, unsigned a1, unsigned a2, unsigned a3,
                                         unsigned b0, unsigned b1) {
    asm volatile(
        "mma.sync.aligned.m16n8k16.row.col.f32.f16.f16.f32 "
        "{%0,%1,%2,%3}, {%4,%5,%6,%7}, {%8,%9}, {%0,%1,%2,%3};"
        : "+f"(c[0]), "+f"(c[1]), "+f"(c[2]), "+f"(c[3])
        : "r"(a0), "r"(a1), "r"(a2), "r"(a3), "r"(b0), "r"(b1));
}

__global__ void __launch_bounds__(THREADS)
gnf_kernel(const float* __restrict__ coords,     // [B, A, 3] f32
           const int*   __restrict__ types_raw,  // [B, A] int32 OR int64 (detected)
           const float* __restrict__ query,      // [B, P, 3] f32
           float*       __restrict__ out)        // [B, P, T, 3] f32
{
    // sAtom[a] = (cx', cy', cz', |c'|^2), c' = c*log2e   -> scalar d^2 dot
    // sBhi/sBlo: B^T [NCOL][KPAD] split-f16; col 4t+{0..3} = (1, cx, cy, cz)
    __shared__ float4 sAtom[AA];
    __shared__ __half sBhi[NCOL * KPAD];
    __shared__ __half sBlo[NCOL * KPAD];
    __shared__ float  sOut[QPB * TT * 3];   // 1920 floats staging for coalesced stores

    const int tid = threadIdx.x;
    const int b   = blockIdx.y;

    // ---- zero B matrices
    for (int i = tid; i < NCOL * KPAD / 2; i += THREADS) {
        ((unsigned*)sBhi)[i] = 0u;
        ((unsigned*)sBlo)[i] = 0u;
    }

    // ---- dtype detection (1 LDG/thread); int64 iff all sampled odd words in {0,-1}
    {
        int w = types_raw[2 * (tid & 255) + 1];
        bool okk = (w == 0) || (w == -1);
        const int is64 = __syncthreads_and(okk ? 1 : 0);   // also fences zero-fill

        if (tid < AA) {
            long long tv;
            if (is64) tv = ((const long long*)types_raw)[(long)b * AA + tid];
            else      tv = (long long)types_raw[(long)b * AA + tid];
            const float* c = coords + ((long)b * AA + tid) * 3;

            if (tv >= 0 && tv < TT) {
                float rx = c[0], ry = c[1], rz = c[2];
                float cx = rx * K_LOG2E, cy = ry * K_LOG2E, cz = rz * K_LOG2E;
                sAtom[tid] = make_float4(cx, cy, cz,
                                         fmaf(cx, cx, fmaf(cy, cy, cz * cz)));
                int t4 = (int)tv * 4;
                sBhi[(t4 + 0) * KPAD + tid] = __float2half_rn(1.f);
                float v[3] = {rx, ry, rz};
                #pragma unroll
                for (int j = 0; j < 3; j++) {
                    __half h = __float2half_rn(v[j]);
                    sBhi[(t4 + 1 + j) * KPAD + tid] = h;
                    sBlo[(t4 + 1 + j) * KPAD + tid] =
                        __float2half_rn(v[j] - __half2float(h));
                }
            } else {
                sAtom[tid] = make_float4(0.f, 0.f, 0.f, 1e30f);  // w -> ex2(-inf) = 0
            }
        }
        __syncthreads();
    }

    // ---- warp owns 16 queries (one m16 tile); lane roles per mma fragment
    const int warp = tid >> 5;
    const int lane = tid & 31;
    const int r    = lane >> 2;        // 0..7
    const int kq   = (lane & 3) * 2;   // 0,2,4,6
    const int qb   = blockIdx.x * QPB + warp * 16;

    const float* qp0 = query + ((long)b * PP + qb + r) * 3;
    const float* qp1 = query + ((long)b * PP + qb + r + 8) * 3;
    const float n0x = qp0[0] * (-2.f * K_LOG2E), n0y = qp0[1] * (-2.f * K_LOG2E),
                n0z = qp0[2] * (-2.f * K_LOG2E);
    const float n1x = qp1[0] * (-2.f * K_LOG2E), n1y = qp1[1] * (-2.f * K_LOG2E),
                n1z = qp1[2] * (-2.f * K_LOG2E);
    const float qq0 = 0.25f * fmaf(n0x, n0x, fmaf(n0y, n0y, n0z * n0z));
    const float qq1 = 0.25f * fmaf(n1x, n1x, fmaf(n1y, n1y, n1z * n1z));

    float acc[3][4];
    #pragma unroll
    for (int nt = 0; nt < 3; nt++)
        #pragma unroll
        for (int j = 0; j < 4; j++) acc[nt][j] = 0.f;

    // ---- main loop: 8 k-tiles of 16 atoms
    #pragma unroll
    for (int kt = 0; kt < 8; kt++) {
        const int k0 = kt * 16 + kq;
        const float4 cA = sAtom[k0];
        const float4 cB = sAtom[k0 + 1];
        const float4 cC = sAtom[k0 + 8];
        const float4 cD = sAtom[k0 + 9];

        float dA0 = fmaf(cA.x, n0x, fmaf(cA.y, n0y, fmaf(cA.z, n0z, cA.w))) + qq0;
        float dB0 = fmaf(cB.x, n0x, fmaf(cB.y, n0y, fmaf(cB.z, n0z, cB.w))) + qq0;
        float dC0 = fmaf(cC.x, n0x, fmaf(cC.y, n0y, fmaf(cC.z, n0z, cC.w))) + qq0;
        float dD0 = fmaf(cD.x, n0x, fmaf(cD.y, n0y, fmaf(cD.z, n0z, cD.w))) + qq0;
        float dA1 = fmaf(cA.x, n1x, fmaf(cA.y, n1y, fmaf(cA.z, n1z, cA.w))) + qq1;
        float dB1 = fmaf(cB.x, n1x, fmaf(cB.y, n1y, fmaf(cB.z, n1z, cB.w))) + qq1;
        float dC1 = fmaf(cC.x, n1x, fmaf(cC.y, n1y, fmaf(cC.z, n1z, cC.w))) + qq1;
        float dD1 = fmaf(cD.x, n1x, fmaf(cD.y, n1y, fmaf(cD.z, n1z, cD.w))) + qq1;

        unsigned a0 = ex2_f16x2(cvt_f16x2(sqrtf_a(dB0), sqrtf_a(dA0)) ^ 0x80008000u);
        unsigned a1 = ex2_f16x2(cvt_f16x2(sqrtf_a(dB1), sqrtf_a(dA1)) ^ 0x80008000u);
        unsigned a2 = ex2_f16x2(cvt_f16x2(sqrtf_a(dD0), sqrtf_a(dC0)) ^ 0x80008000u);
        unsigned a3 = ex2_f16x2(cvt_f16x2(sqrtf_a(dD1), sqrtf_a(dC1)) ^ 0x80008000u);

        // load all fragments, then issue hi[0..2] lo[0..2]: RAW distance 1 -> 3
        unsigned bh0[3], bh1[3], bl0[3], bl1[3];
        #pragma unroll
        for (int nt = 0; nt < 3; nt++) {
            const int bbase = (nt * 8 + r) * KPAD + kt * 16 + kq;
            bh0[nt] = *(const unsigned*)&sBhi[bbase];
            bh1[nt] = *(const unsigned*)&sBhi[bbase + 8];
            bl0[nt] = *(const unsigned*)&sBlo[bbase];
            bl1[nt] = *(const unsigned*)&sBlo[bbase + 8];
        }
        #pragma unroll
        for (int nt = 0; nt < 3; nt++)
            mma16816(acc[nt], a0, a1, a2, a3, bh0[nt], bh1[nt]);
        #pragma unroll
        for (int nt = 0; nt < 3; nt++)
            mma16816(acc[nt], a0, a1, a2, a3, bl0[nt], bl1[nt]);
    }

    // ---- epilogue: fragments -> (S,Gx,Gy,Gz), finalize, stage to smem
    #pragma unroll
    for (int nt = 0; nt < 3; nt++) {
        float c0 = acc[nt][0], c1 = acc[nt][1], c2 = acc[nt][2], c3 = acc[nt][3];
        float x0 = __shfl_xor_sync(0xffffffffu, c0, 1);
        float x1 = __shfl_xor_sync(0xffffffffu, c1, 1);
        float x2 = __shfl_xor_sync(0xffffffffu, c2, 1);
        float x3 = __shfl_xor_sync(0xffffffffu, c3, 1);

        const int t = 2 * nt + ((lane & 3) >> 1);
        if (t < TT) {
            float S, Gx, Gy, Gz;
            int ql;   // query index local to block
            if ((lane & 1) == 0) { S = c0; Gx = c1; Gy = x0; Gz = x1; ql = warp * 16 + r; }
            else                 { S = x2; Gx = x3; Gy = c2; Gz = c3; ql = warp * 16 + r + 8; }

            const float* qp = query + ((long)b * PP + blockIdx.x * QPB + ql) * 3;
            float gx = 0.f, gy = 0.f, gz = 0.f;
            if (S > 0.f) {
                float inv = rcpf_a(S);
                gx = fmaf(Gx, inv, -qp[0]);
                gy = fmaf(Gy, inv, -qp[1]);
                gz = fmaf(Gz, inv, -qp[2]);
                float m2 = fmaf(gx, gx, fmaf(gy, gy, gz * gz));
                if (m2 > CLIP * CLIP) {
                    float sc = CLIP * rsqrtf_a(m2);
                    gx *= sc; gy *= sc; gz *= sc;
                }
            }
            float* op = &sOut[(ql * TT + t) * 3];
            op[0] = gx; op[1] = gy; op[2] = gz;
        }
    }
    __syncthreads();

    // ---- coalesced block store: 1920 contiguous floats = 480 float4
    {
        float4* dst = (float4*)(out + ((long)b * PP + (long)blockIdx.x * QPB) * (TT * 3));
        const float4* src = (const float4*)sOut;
        #pragma unroll 2
        for (int i = tid; i < QPB * TT * 3 / 4; i += THREADS)
            dst[i] = src[i];
    }
}

extern "C" void kernel_launch(void* const* d_in, const int* in_sizes, int n_in,
                              void* d_out, int out_size)
{
    const float* coords = (const float*)d_in[0];   // [16,128,3] f32
    const int*   types  = (const int*)d_in[1];     // [16,128] int32/int64 (detected on device)
    const float* query  = (const float*)d_in[2];   // [16,8192,3] f32
    float*       out    = (float*)d_out;           // [16,8192,5,3] f32

    dim3 grid(PP / QPB, BB);   // (64, 16) = 1024 blocks x 256 threads
    gnf_kernel<<<grid, THREADS>>>(coords, types, query, out);
}

// round 13
// speedup vs baseline: 1.0991x; 1.0052x over previous
#include <cuda_runtime.h>
#include <cuda_fp16.h>

// Problem constants (from reference)
#define BB 16
#define AA 128
#define PP 8192
#define TT 5
#define K_LOG2E 1.4426950408889634f   // log2(e); TEMPERATURE = 1.0
#define CLIP    0.3f

#define THREADS 256        // 8 warps/block
#define QPB 128            // queries per block: each warp owns 16 queries
#define NCOL 24            // B columns: 5 types * 4 (S,Gx,Gy,Gz), padded to 24
#define KPAD 136           // padded k-stride (halves): bank-conflict-free

__device__ __forceinline__ float sqrtf_a(float x) {
    float y; asm("sqrt.approx.ftz.f32 %0, %1;" : "=f"(y) : "f"(x)); return y;
}
__device__ __forceinline__ float rcpf_a(float x) {
    float y; asm("rcp.approx.ftz.f32 %0, %1;" : "=f"(y) : "f"(x)); return y;
}
__device__ __forceinline__ float rsqrtf_a(float x) {
    float y; asm("rsqrt.approx.ftz.f32 %0, %1;" : "=f"(y) : "f"(x)); return y;
}
// cvt two f32 -> f16x2; FIRST operand lands in the HIGH half
__device__ __forceinline__ unsigned cvt_f16x2(float hi, float lo) {
    unsigned r; asm("cvt.rn.f16x2.f32 %0, %1, %2;" : "=r"(r) : "f"(hi), "f"(lo)); return r;
}
__device__ __forceinline__ unsigned ex2_f16x2(unsigned x) {
    unsigned r; asm("ex2.approx.f16x2 %0, %1;" : "=r"(r) : "r"(x)); return r;
}
// ldmatrix x4 (no trans): smem rows are B^T rows -> direct mma B fragments
__device__ __forceinline__ void ldsm_x4(unsigned& d0, unsigned& d1,
                                        unsigned& d2, unsigned& d3, unsigned addr) {
    asm volatile("ldmatrix.sync.aligned.m8n8.x4.shared.b16 {%0,%1,%2,%3}, [%4];"
                 : "=r"(d0), "=r"(d1), "=r"(d2), "=r"(d3) : "r"(addr));
}
// D += A(16x16 f16) * B(16x8 f16), f32 accumulate
__device__ __forceinline__ void mma16816(float* c,
                                         unsigned a0, unsigned a1, unsigned a2, unsigned a3,
                                         unsigned b0, unsigned b1) {
    asm volatile(
        "mma.sync.aligned.m16n8k16.row.col.f32.f16.f16.f32 "
        "{%0,%1,%2,%3}, {%4,%5,%6,%7}, {%8,%9}, {%0,%1,%2,%3};"
        : "+f"(c[0]), "+f"(c[1]), "+f"(c[2]), "+f"(c[3])
        : "r"(a0), "r"(a1), "r"(a2), "r"(a3), "r"(b0), "r"(b1));
}

__global__ void __launch_bounds__(THREADS)
gnf_kernel(const float* __restrict__ coords,     // [B, A, 3] f32
           const int*   __restrict__ types_raw,  // [B, A] int32 OR int64 (detected)
           const float* __restrict__ query,      // [B, P, 3] f32
           float*       __restrict__ out)        // [B, P, T, 3] f32
{
    // sAtom[a] = (cx', cy', cz', |c'|^2), c' = c*log2e   -> scalar d^2 dot
    // sBhi/sBlo: B^T [NCOL][KPAD] split-f16; col 4t+{0..3} = (1, cx, cy, cz)
    __shared__ float4 sAtom[AA];
    __shared__ __half sBhi[NCOL * KPAD];
    __shared__ __half sBlo[NCOL * KPAD];
    __shared__ float  sOut[QPB * TT * 3];   // staging for coalesced stores

    const int tid = threadIdx.x;
    const int b   = blockIdx.y;

    // ---- zero B matrices
    for (int i = tid; i < NCOL * KPAD / 2; i += THREADS) {
        ((unsigned*)sBhi)[i] = 0u;
        ((unsigned*)sBlo)[i] = 0u;
    }

    // ---- dtype detection (1 LDG/thread); int64 iff all sampled odd words in {0,-1}
    {
        int w = types_raw[2 * (tid & 255) + 1];
        bool okk = (w == 0) || (w == -1);
        const int is64 = __syncthreads_and(okk ? 1 : 0);   // also fences zero-fill

        if (tid < AA) {
            long long tv;
            if (is64) tv = ((const long long*)types_raw)[(long)b * AA + tid];
            else      tv = (long long)types_raw[(long)b * AA + tid];
            const float* c = coords + ((long)b * AA + tid) * 3;

            if (tv >= 0 && tv < TT) {
                float rx = c[0], ry = c[1], rz = c[2];
                float cx = rx * K_LOG2E, cy = ry * K_LOG2E, cz = rz * K_LOG2E;
                sAtom[tid] = make_float4(cx, cy, cz,
                                         fmaf(cx, cx, fmaf(cy, cy, cz * cz)));
                int t4 = (int)tv * 4;
                sBhi[(t4 + 0) * KPAD + tid] = __float2half_rn(1.f);
                float v[3] = {rx, ry, rz};
                #pragma unroll
                for (int j = 0; j < 3; j++) {
                    __half h = __float2half_rn(v[j]);
                    sBhi[(t4 + 1 + j) * KPAD + tid] = h;
                    sBlo[(t4 + 1 + j) * KPAD + tid] =
                        __float2half_rn(v[j] - __half2float(h));
                }
            } else {
                sAtom[tid] = make_float4(0.f, 0.f, 0.f, 1e30f);  // w -> ex2(-inf) = 0
            }
        }
        __syncthreads();
    }

    // ---- warp owns 16 queries (one m16 tile); lane roles per mma fragment
    const int warp = tid >> 5;
    const int lane = tid & 31;
    const int r    = lane >> 2;        // 0..7
    const int kq   = (lane & 3) * 2;   // 0,2,4,6
    const int qb   = blockIdx.x * QPB + warp * 16;

    // ldmatrix lane pointers (bytes, shared address space)
    const unsigned sbhi = (unsigned)__cvta_generic_to_shared(sBhi);
    const unsigned sblo = (unsigned)__cvta_generic_to_shared(sBlo);
    const int lg = lane >> 3;               // ldmatrix 8-lane group 0..3
    const int lr = lane & 7;                // row within group
    const unsigned kh = (unsigned)((lg & 1) * 16);   // k-half byte offset
    // L0: hi nt0 (g0,g1), hi nt1 (g2,g3)
    const unsigned p0 = sbhi + (unsigned)(((lg >> 1) * 8 + lr) * KPAD * 2) + kh;
    // L1: hi nt2 (g0,g1), lo nt0 (g2,g3)
    const unsigned p1 = (lg < 2)
        ? sbhi + (unsigned)((16 + lr) * KPAD * 2) + kh
        : sblo + (unsigned)(lr * KPAD * 2) + kh;
    // L2: lo nt1 (g0,g1), lo nt2 (g2,g3)
    const unsigned p2 = sblo + (unsigned)((((lg >> 1) + 1) * 8 + lr) * KPAD * 2) + kh;

    const float* qp0 = query + ((long)b * PP + qb + r) * 3;
    const float* qp1 = query + ((long)b * PP + qb + r + 8) * 3;
    const float n0x = qp0[0] * (-2.f * K_LOG2E), n0y = qp0[1] * (-2.f * K_LOG2E),
                n0z = qp0[2] * (-2.f * K_LOG2E);
    const float n1x = qp1[0] * (-2.f * K_LOG2E), n1y = qp1[1] * (-2.f * K_LOG2E),
                n1z = qp1[2] * (-2.f * K_LOG2E);
    const float qq0 = 0.25f * fmaf(n0x, n0x, fmaf(n0y, n0y, n0z * n0z));
    const float qq1 = 0.25f * fmaf(n1x, n1x, fmaf(n1y, n1y, n1z * n1z));

    float acc[3][4];
    #pragma unroll
    for (int nt = 0; nt < 3; nt++)
        #pragma unroll
        for (int j = 0; j < 4; j++) acc[nt][j] = 0.f;

    // ---- main loop: 8 k-tiles of 16 atoms
    #pragma unroll
    for (int kt = 0; kt < 8; kt++) {
        const int k0 = kt * 16 + kq;
        const float4 cA = sAtom[k0];
        const float4 cB = sAtom[k0 + 1];
        const float4 cC = sAtom[k0 + 8];
        const float4 cD = sAtom[k0 + 9];

        float dA0 = fmaf(cA.x, n0x, fmaf(cA.y, n0y, fmaf(cA.z, n0z, cA.w))) + qq0;
        float dB0 = fmaf(cB.x, n0x, fmaf(cB.y, n0y, fmaf(cB.z, n0z, cB.w))) + qq0;
        float dC0 = fmaf(cC.x, n0x, fmaf(cC.y, n0y, fmaf(cC.z, n0z, cC.w))) + qq0;
        float dD0 = fmaf(cD.x, n0x, fmaf(cD.y, n0y, fmaf(cD.z, n0z, cD.w))) + qq0;
        float dA1 = fmaf(cA.x, n1x, fmaf(cA.y, n1y, fmaf(cA.z, n1z, cA.w))) + qq1;
        float dB1 = fmaf(cB.x, n1x, fmaf(cB.y, n1y, fmaf(cB.z, n1z, cB.w))) + qq1;
        float dC1 = fmaf(cC.x, n1x, fmaf(cC.y, n1y, fmaf(cC.z, n1z, cC.w))) + qq1;
        float dD1 = fmaf(cD.x, n1x, fmaf(cD.y, n1y, fmaf(cD.z, n1z, cD.w))) + qq1;

        // B fragments via 3 ldmatrix.x4 (12 LDS.32 -> 3 LDSM)
        const unsigned koff = (unsigned)(kt * 32);
        unsigned h00, h01, h10, h11;   // hi nt0 {b0,b1}, hi nt1 {b0,b1}
        unsigned h20, h21, l00, l01;   // hi nt2 {b0,b1}, lo nt0 {b0,b1}
        unsigned l10, l11, l20, l21;   // lo nt1 {b0,b1}, lo nt2 {b0,b1}
        ldsm_x4(h00, h01, h10, h11, p0 + koff);
        ldsm_x4(h20, h21, l00, l01, p1 + koff);
        ldsm_x4(l10, l11, l20, l21, p2 + koff);

        unsigned a0 = ex2_f16x2(cvt_f16x2(sqrtf_a(dB0), sqrtf_a(dA0)) ^ 0x80008000u);
        unsigned a1 = ex2_f16x2(cvt_f16x2(sqrtf_a(dB1), sqrtf_a(dA1)) ^ 0x80008000u);
        unsigned a2 = ex2_f16x2(cvt_f16x2(sqrtf_a(dD0), sqrtf_a(dC0)) ^ 0x80008000u);
        unsigned a3 = ex2_f16x2(cvt_f16x2(sqrtf_a(dD1), sqrtf_a(dC1)) ^ 0x80008000u);

        // hi then lo: accumulator RAW distance 3
        mma16816(acc[0], a0, a1, a2, a3, h00, h01);
        mma16816(acc[1], a0, a1, a2, a3, h10, h11);
        mma16816(acc[2], a0, a1, a2, a3, h20, h21);
        mma16816(acc[0], a0, a1, a2, a3, l00, l01);
        mma16816(acc[1], a0, a1, a2, a3, l10, l11);
        mma16816(acc[2], a0, a1, a2, a3, l20, l21);
    }

    // ---- epilogue: fragments -> (S,Gx,Gy,Gz), finalize, stage to smem
    #pragma unroll
    for (int nt = 0; nt < 3; nt++) {
        float c0 = acc[nt][0], c1 = acc[nt][1], c2 = acc[nt][2], c3 = acc[nt][3];
        float x0 = __shfl_xor_sync(0xffffffffu, c0, 1);
        float x1 = __shfl_xor_sync(0xffffffffu, c1, 1);
        float x2 = __shfl_xor_sync(0xffffffffu, c2, 1);
        float x3 = __shfl_xor_sync(0xffffffffu, c3, 1);

        const int t = 2 * nt + ((lane & 3) >> 1);
        if (t < TT) {
            float S, Gx, Gy, Gz;
            int ql;   // query index local to block
            if ((lane & 1) == 0) { S = c0; Gx = c1; Gy = x0; Gz = x1; ql = warp * 16 + r; }
            else                 { S = x2; Gx = x3; Gy = c2; Gz = c3; ql = warp * 16 + r + 8; }

            const float* qp = query + ((long)b * PP + blockIdx.x * QPB + ql) * 3;
            float gx = 0.f, gy = 0.f, gz = 0.f;
            if (S > 0.f) {
                float inv = rcpf_a(S);
                gx = fmaf(Gx, inv, -qp[0]);
                gy = fmaf(Gy, inv, -qp[1]);
                gz = fmaf(Gz, inv, -qp[2]);
                float m2 = fmaf(gx, gx, fmaf(gy, gy, gz * gz));
                if (m2 > CLIP * CLIP) {
                    float sc = CLIP * rsqrtf_a(m2);
                    gx *= sc; gy *= sc; gz *= sc;
                }
            }
            float* op = &sOut[(ql * TT + t) * 3];
            op[0] = gx; op[1] = gy; op[2] = gz;
        }
    }
    __syncthreads();

    // ---- coalesced block store: 1920 contiguous floats = 480 float4
    {
        float4* dst = (float4*)(out + ((long)b * PP + (long)blockIdx.x * QPB) * (TT * 3));
        const float4* src = (const float4*)sOut;
        #pragma unroll 2
        for (int i = tid; i < QPB * TT * 3 / 4; i += THREADS)
            dst[i] = src[i];
    }
}

extern "C" void kernel_launch(void* const* d_in, const int* in_sizes, int n_in,
                              void* d_out, int out_size)
{
    const float* coords = (const float*)d_in[0];   // [16,128,3] f32
    const int*   types  = (const int*)d_in[1];     // [16,128] int32/int64 (detected on device)
    const float* query  = (const float*)d_in[2];   // [16,8192,3] f32
    float*       out    = (float*)d_out;           // [16,8192,5,3] f32

    dim3 grid(PP / QPB, BB);   // (64, 16) = 1024 blocks x 256 threads
    gnf_kernel<<<grid, THREADS>>>(coords, types, query, out);
}